// round 16
// baseline (speedup 1.0000x reference)
#include <cuda_runtime.h>
#include <cuda_bf16.h>
#include <math.h>
#include <stdint.h>

#define BATCH   2
#define NNODE   32768
#define DIM     128
#define ZDIM    256
#define OUTD    128
#define HEADS   8
#define NEDGE   262144
#define NODES_TOT (BATCH*NNODE)   /* 65536  */
#define EDGES_TOT (BATCH*NEDGE)   /* 524288 */
#define NEG_SLOPE 0.01f

// ---------------- scratch (static device allocations; no cudaMalloc) ----------------
__device__ float g_att1[NODES_TOT*HEADS];
__device__ float g_att2[NODES_TOT*HEADS];
__device__ float g_v[NODES_TOT*OUTD];
__device__ float g_skip[NODES_TOT*OUTD];
__device__ float g_hidden2[NODES_TOT*OUTD];
__device__ float g_sumv[NODES_TOT*HEADS];   // zero-init; finalize re-zeros (race-free)
__device__ float g_agg[NODES_TOT*OUTD];     // zero-init; finalize re-zeros
__device__ float g_ae[EDGES_TOT*HEADS];     // precomputed ef@Wae + bae
__device__ float g_pv[NODES_TOT*256];       // node_fts @ W[0:128,:]
__device__ float g_attp[NODES_TOT*16];      // node_fts @ Wa[0:128,:]
__device__ float g_bcat[256];
__device__ float g_Wa[ZDIM*16];
__device__ float g_ba[16];
__device__ unsigned short g_Wt_hi[256*256];
__device__ unsigned short g_Wt_lo[256*256];

// ---------------- helpers ----------------
__device__ __forceinline__ uint32_t smem_to_u32(const void* smem_ptr) {
    uint32_t addr;
    asm("{ .reg .u64 tmp; cvta.to.shared.u64 tmp, %1; cvt.u32.u64 %0, tmp; }"
        : "=r"(addr) : "l"(smem_ptr));
    return addr;
}
__device__ __forceinline__ void ldsm4(uint32_t* r, uint32_t addr){
    asm volatile("ldmatrix.sync.aligned.m8n8.x4.shared.b16 {%0,%1,%2,%3}, [%4];"
        : "=r"(r[0]), "=r"(r[1]), "=r"(r[2]), "=r"(r[3]) : "r"(addr));
}
__device__ __forceinline__ void mma_bf16(float* c, const uint32_t* a, uint32_t b0, uint32_t b1){
    asm volatile("mma.sync.aligned.m16n8k16.row.col.f32.bf16.bf16.f32 "
        "{%0,%1,%2,%3}, {%4,%5,%6,%7}, {%8,%9}, {%0,%1,%2,%3};"
        : "+f"(c[0]), "+f"(c[1]), "+f"(c[2]), "+f"(c[3])
        : "r"(a[0]), "r"(a[1]), "r"(a[2]), "r"(a[3]), "r"(b0), "r"(b1));
}
__device__ __forceinline__ void split1(float a, unsigned short& h, unsigned short& l){
    __nv_bfloat16 hb = __float2bfloat16(a);
    __nv_bfloat16 lb = __float2bfloat16(a - __bfloat162float(hb));
    h = __bfloat16_as_ushort(hb); l = __bfloat16_as_ushort(lb);
}
__device__ __forceinline__ uint32_t pack2(unsigned short a, unsigned short b){
    return (uint32_t)a | ((uint32_t)b << 16);
}
__device__ __forceinline__ void cp16(uint32_t dst, const void* src){
    asm volatile("cp.async.ca.shared.global [%0], [%1], 16;" :: "r"(dst), "l"(src));
}
#define CP_COMMIT()  asm volatile("cp.async.commit_group;" ::: "memory")
#define CP_WAIT0()   asm volatile("cp.async.wait_group 0;" ::: "memory")
#define CP_WAIT1()   asm volatile("cp.async.wait_group 1;" ::: "memory")
__device__ __forceinline__ void red_add4(float* p, float4 m){
    asm volatile("red.global.add.v4.f32 [%0], {%1,%2,%3,%4};"
                 :: "l"(p), "f"(m.x), "f"(m.y), "f"(m.z), "f"(m.w) : "memory");
}

// ---------------- weight packing ----------------
__global__ void build_w(const float* __restrict__ Wm, const float* __restrict__ Wskip){
    int i = blockIdx.x*blockDim.x + threadIdx.x;
    if (i < 256*256){
        int n = i >> 8, k = i & 255;
        float w = (n < OUTD) ? Wm[k*OUTD + n] : Wskip[k*OUTD + (n - OUTD)];
        unsigned short h, l;
        split1(w, h, l);
        g_Wt_hi[i] = h; g_Wt_lo[i] = l;
    }
}
__global__ void build_wa(const float* __restrict__ Wa1, const float* __restrict__ Wa2,
                         const float* __restrict__ ba1, const float* __restrict__ ba2){
    int i = blockIdx.x*blockDim.x + threadIdx.x;
    if (i < ZDIM*16){
        int k = i >> 4, j = i & 15;
        g_Wa[i] = (j < HEADS) ? Wa1[k*HEADS + j] : Wa2[k*HEADS + (j-HEADS)];
    }
    if (i < 16) g_ba[i] = (i < HEADS) ? ba1[i] : ba2[i-HEADS];
}
__global__ void build_wb(const float* __restrict__ bm, const float* __restrict__ bskip){
    int i = threadIdx.x;
    if (i < 256) g_bcat[i] = (i < OUTD) ? bm[i] : bskip[i-OUTD];
}

// ---------------- ae precompute: cp.async double-buffered (R13 proven) ----------------
#define AE_TILES_PER_BLK 8
#define AE_BUF_F4 (32*36)
__global__ void __launch_bounds__(256) ae_gkt(const float* __restrict__ ef,
                                              const float* __restrict__ Wae,
                                              const float* __restrict__ bae){
    __shared__ float4 sz[2*AE_BUF_F4];
    const uint32_t sb = smem_to_u32(sz);
    const int tid = threadIdx.x;
    const int lane = tid & 31;
    const int wid = tid >> 5;
    const int q = lane >> 3, h = lane & 7;
    float w[32];
    #pragma unroll
    for (int i = 0; i < 32; i++) w[i] = Wae[(q*32 + i)*HEADS + h];
    const float bb = bae[h];

    const size_t tile0 = (size_t)blockIdx.x * AE_TILES_PER_BLK;

    #pragma unroll
    for (int r = 0; r < 4; r++){
        int f = tid + 256*r;
        int e = f >> 5, j = f & 31;
        uint32_t dst = sb + (uint32_t)(e*36 + (j >> 3)*9 + (j & 7))*16u;
        cp16(dst, ef + (tile0*32 + e)*DIM + j*4);
    }
    CP_COMMIT();

    #pragma unroll 1
    for (int t = 0; t < AE_TILES_PER_BLK; t++){
        if (t + 1 < AE_TILES_PER_BLK){
            uint32_t bufo = ((t+1) & 1) ? (uint32_t)AE_BUF_F4*16u : 0u;
            #pragma unroll
            for (int r = 0; r < 4; r++){
                int f = tid + 256*r;
                int e = f >> 5, j = f & 31;
                uint32_t dst = sb + bufo + (uint32_t)(e*36 + (j >> 3)*9 + (j & 7))*16u;
                cp16(dst, ef + ((tile0 + t + 1)*32 + e)*DIM + j*4);
            }
            CP_COMMIT();
            CP_WAIT1();
        } else {
            CP_WAIT0();
        }
        __syncthreads();

        const float4* buf = sz + ((t & 1) ? AE_BUF_F4 : 0);
        #pragma unroll
        for (int eo = 0; eo < 4; eo++){
            int el = wid*4 + eo;
            float acc = 0.0f;
            #pragma unroll
            for (int i = 0; i < 8; i++){
                float4 v = buf[el*36 + q*9 + i];
                acc += v.x*w[4*i] + v.y*w[4*i+1] + v.z*w[4*i+2] + v.w*w[4*i+3];
            }
            acc += __shfl_xor_sync(0xffffffffu, acc, 8);
            acc += __shfl_xor_sync(0xffffffffu, acc, 16);
            if (lane < 8) g_ae[((tile0 + t)*32 + el)*HEADS + h] = acc + bb;
        }
        __syncthreads();
    }
}

// ================= node GEMM (K=128 half): mma.sync bf16 3-term, cp.async ==================
#define SM_AHI     0
#define SM_ALO     10240
#define SM_B0      20480
#define B_BUF_SZ   20480
#define GEMM_SMEM  61440

__global__ void __launch_bounds__(256, 2) gemm_node(const float* __restrict__ fin, int mode){
    const float* f = (mode == 2) ? g_hidden2 : fin;
    const int koffB = (mode == 0) ? 0 : 128;
    extern __shared__ char sm[];
    const uint32_t sb = smem_to_u32(sm);
    const int tid  = threadIdx.x;
    const int lane = tid & 31;
    const int wid  = tid >> 5;
    const int wm   = (wid >> 1) * 32;
    const int wn   = (wid & 1) * 64;
    const int row0g = blockIdx.x * 128;
    const int n0g   = blockIdx.y * 128;

    float acc[2][8][4];
    #pragma unroll
    for (int a = 0; a < 2; a++)
        #pragma unroll
        for (int b = 0; b < 8; b++)
            #pragma unroll
            for (int c = 0; c < 4; c++) acc[a][b][c] = 0.0f;

    const int arow = tid >> 1, ah16 = (tid & 1) * 16;
    const int bn = tid >> 1,  hb = tid & 1;
    const int grp = lane >> 3, wi = lane & 7;

    {
        uint32_t bdst = sb + SM_B0 + bn*80 + hb*32;
        const unsigned short* src_h = g_Wt_hi + (size_t)(n0g + bn)*256 + koffB + hb*16;
        const unsigned short* src_l = g_Wt_lo + (size_t)(n0g + bn)*256 + koffB + hb*16;
        cp16(bdst,              src_h);
        cp16(bdst + 16,         src_h + 8);
        cp16(bdst + 10240,      src_l);
        cp16(bdst + 10240 + 16, src_l + 8);
        CP_COMMIT();
    }
    float4 ap0, ap1, ap2, ap3;
    {
        const float* ap = f + (size_t)(row0g + arow)*DIM + ah16;
        ap0 = *(const float4*)ap;       ap1 = *(const float4*)(ap + 4);
        ap2 = *(const float4*)(ap + 8); ap3 = *(const float4*)(ap + 12);
    }

    for (int kc = 0; kc < 4; kc++){
        const uint32_t bbase = sb + SM_B0 + (kc & 1)*B_BUF_SZ;

        CP_WAIT0();
        __syncthreads();

        if (kc < 3){
            uint32_t bdst = sb + SM_B0 + ((kc+1) & 1)*B_BUF_SZ + bn*80 + hb*32;
            const unsigned short* src_h = g_Wt_hi + (size_t)(n0g + bn)*256 + koffB + (kc+1)*32 + hb*16;
            const unsigned short* src_l = g_Wt_lo + (size_t)(n0g + bn)*256 + koffB + (kc+1)*32 + hb*16;
            cp16(bdst,              src_h);
            cp16(bdst + 16,         src_h + 8);
            cp16(bdst + 10240,      src_l);
            cp16(bdst + 10240 + 16, src_l + 8);
            CP_COMMIT();
        }

        {
            unsigned short h[16], l[16];
            split1(ap0.x, h[0], l[0]);  split1(ap0.y, h[1], l[1]);
            split1(ap0.z, h[2], l[2]);  split1(ap0.w, h[3], l[3]);
            split1(ap1.x, h[4], l[4]);  split1(ap1.y, h[5], l[5]);
            split1(ap1.z, h[6], l[6]);  split1(ap1.w, h[7], l[7]);
            split1(ap2.x, h[8], l[8]);  split1(ap2.y, h[9], l[9]);
            split1(ap2.z, h[10],l[10]); split1(ap2.w, h[11],l[11]);
            split1(ap3.x, h[12],l[12]); split1(ap3.y, h[13],l[13]);
            split1(ap3.z, h[14],l[14]); split1(ap3.w, h[15],l[15]);
            uint4 hh0, hh1, ll0, ll1;
            hh0.x = pack2(h[0],h[1]);   hh0.y = pack2(h[2],h[3]);
            hh0.z = pack2(h[4],h[5]);   hh0.w = pack2(h[6],h[7]);
            hh1.x = pack2(h[8],h[9]);   hh1.y = pack2(h[10],h[11]);
            hh1.z = pack2(h[12],h[13]); hh1.w = pack2(h[14],h[15]);
            ll0.x = pack2(l[0],l[1]);   ll0.y = pack2(l[2],l[3]);
            ll0.z = pack2(l[4],l[5]);   ll0.w = pack2(l[6],l[7]);
            ll1.x = pack2(l[8],l[9]);   ll1.y = pack2(l[10],l[11]);
            ll1.z = pack2(l[12],l[13]); ll1.w = pack2(l[14],l[15]);
            *(uint4*)(sm + SM_AHI + arow*80 + ah16*2)      = hh0;
            *(uint4*)(sm + SM_AHI + arow*80 + ah16*2 + 16) = hh1;
            *(uint4*)(sm + SM_ALO + arow*80 + ah16*2)      = ll0;
            *(uint4*)(sm + SM_ALO + arow*80 + ah16*2 + 16) = ll1;
        }
        if (kc < 3){
            const float* ap = f + (size_t)(row0g + arow)*DIM + (kc+1)*32 + ah16;
            ap0 = *(const float4*)ap;       ap1 = *(const float4*)(ap + 4);
            ap2 = *(const float4*)(ap + 8); ap3 = *(const float4*)(ap + 12);
        }
        __syncthreads();

        #pragma unroll
        for (int ks = 0; ks < 2; ks++){
            const int kb = ks*16;
            uint32_t ahr[2][4], alr[2][4];
            #pragma unroll
            for (int mt = 0; mt < 2; mt++){
                int r = wm + mt*16 + wi + (grp & 1)*8;
                int c = kb + (grp >> 1)*8;
                uint32_t adr = sb + SM_AHI + r*80 + c*2;
                ldsm4(ahr[mt], adr);
                ldsm4(alr[mt], adr + (SM_ALO - SM_AHI));
            }
            #pragma unroll
            for (int np = 0; np < 4; np++){
                int rb = wn + np*16 + wi + (grp >> 1)*8;
                int cb = kb + (grp & 1)*8;
                uint32_t badr = bbase + rb*80 + cb*2;
                uint32_t bh[4], bl[4];
                ldsm4(bh, badr);
                ldsm4(bl, badr + 10240);
                #pragma unroll
                for (int mt = 0; mt < 2; mt++){
                    #pragma unroll
                    for (int nt = 0; nt < 2; nt++){
                        float* C = acc[mt][np*2 + nt];
                        mma_bf16(C, ahr[mt], bh[nt*2], bh[nt*2+1]);
                        mma_bf16(C, alr[mt], bh[nt*2], bh[nt*2+1]);
                        mma_bf16(C, ahr[mt], bl[nt*2], bl[nt*2+1]);
                    }
                }
            }
        }
    }

    // ---- epilogue ----
    const int gid = lane >> 2, tc = lane & 3;
    if (mode == 0){
        #pragma unroll
        for (int mt = 0; mt < 2; mt++){
            int r0 = row0g + wm + mt*16 + gid;
            #pragma unroll
            for (int np = 0; np < 4; np++){
                #pragma unroll
                for (int nt = 0; nt < 2; nt++){
                    int col = n0g + wn + np*16 + nt*8 + tc*2;
                    float* C = acc[mt][np*2 + nt];
                    float2 o0; o0.x = C[0]; o0.y = C[1];
                    float2 o1; o1.x = C[2]; o1.y = C[3];
                    *(float2*)(g_pv + (size_t)r0*256 + col)     = o0;
                    *(float2*)(g_pv + (size_t)(r0+8)*256 + col) = o1;
                }
            }
        }
    } else {
        #pragma unroll
        for (int mt = 0; mt < 2; mt++){
            int r0 = row0g + wm + mt*16 + gid;
            #pragma unroll
            for (int np = 0; np < 4; np++){
                #pragma unroll
                for (int nt = 0; nt < 2; nt++){
                    int col = n0g + wn + np*16 + nt*8 + tc*2;
                    float* dst = (col < 128) ? g_v : g_skip;
                    int cl = col & 127;
                    float b0 = g_bcat[col], b1 = g_bcat[col + 1];
                    float2 p0 = *(const float2*)(g_pv + (size_t)r0*256 + col);
                    float2 p1 = *(const float2*)(g_pv + (size_t)(r0+8)*256 + col);
                    float* C = acc[mt][np*2 + nt];
                    float2 o0; o0.x = C[0] + p0.x + b0; o0.y = C[1] + p0.y + b1;
                    float2 o1; o1.x = C[2] + p1.x + b0; o1.y = C[3] + p1.y + b1;
                    *(float2*)(dst + (size_t)r0*OUTD + cl)     = o0;
                    *(float2*)(dst + (size_t)(r0+8)*OUTD + cl) = o1;
                }
            }
        }
    }
}

// ---------------- attention-vector GEMM (K=128 half) ----------------
__global__ void __launch_bounds__(256) gemm_att(const float* __restrict__ fin, int mode){
    const float* base = (mode == 2) ? g_hidden2 : fin;
    const int koff = (mode == 0) ? 0 : 128;
    __shared__ float As2[128][36];
    __shared__ float Bs[32][16];
    const int t = threadIdx.x;
    const int row0 = blockIdx.x * 128;
    const int my = t >> 1, tx = t & 1;
    float acc[8] = {0,0,0,0,0,0,0,0};

    for (int kc = 0; kc < DIM; kc += 32){
        #pragma unroll
        for (int i = 0; i < 4; i++){
            int id = t + 256*i;
            int r = id >> 3, q = id & 7;
            float4 g = *(const float4*)(base + (size_t)(row0 + r)*DIM + kc + q*4);
            *(float4*)(&As2[r][q*4]) = g;
        }
        if (t < 128){
            int kk = t >> 2, j4 = (t & 3)*4;
            *(float4*)(&Bs[kk][j4]) = *(const float4*)(g_Wa + (koff + kc + kk)*16 + j4);
        }
        __syncthreads();
        #pragma unroll
        for (int kk = 0; kk < 32; kk++){
            float a = As2[my][kk];
            float4 b0 = *(float4*)(&Bs[kk][tx*8]);
            float4 b1 = *(float4*)(&Bs[kk][tx*8 + 4]);
            acc[0] = fmaf(a, b0.x, acc[0]); acc[1] = fmaf(a, b0.y, acc[1]);
            acc[2] = fmaf(a, b0.z, acc[2]); acc[3] = fmaf(a, b0.w, acc[3]);
            acc[4] = fmaf(a, b1.x, acc[4]); acc[5] = fmaf(a, b1.y, acc[5]);
            acc[6] = fmaf(a, b1.z, acc[6]); acc[7] = fmaf(a, b1.w, acc[7]);
        }
        __syncthreads();
    }

    int row = row0 + my;
    if (mode == 0){
        #pragma unroll
        for (int jj = 0; jj < 8; jj++)
            g_attp[row*16 + tx*8 + jj] = acc[jj];
    } else {
        #pragma unroll
        for (int jj = 0; jj < 8; jj++){
            int j = tx*8 + jj;
            float v = acc[jj] + g_attp[row*16 + j] + g_ba[j];
            if (j < HEADS) g_att1[row*HEADS + j] = v;
            else           g_att2[row*HEADS + (j-HEADS)] = v;
        }
    }
}

// ---------------- fused edge pass v2 (cfg): 8 threads/edge, 4x MLP ----------------
// Lane h owns head h: logit/exp/sumv + v-floats [h*16, h*16+16) gathered and
// scattered as 4 independent float4 ops (no shfl, no idle lanes).
__global__ void __launch_bounds__(256) edge_pass_cfg(const int* __restrict__ idx){
    int tid = threadIdx.x;
    int h = tid & 7;
    int e = blockIdx.x*32 + (tid >> 3);
    int base = (e >= NEDGE) ? NNODE : 0;
    int2 st = *(const int2*)(idx + 2*e);
    int s = st.x, tg = st.y;
    float l = g_att1[(base+s)*HEADS + h] + g_att2[(base+tg)*HEADS + h];
    l = (l > 0.0f) ? l : NEG_SLOPE*l;
    float ex = __expf(l);
    asm volatile("red.global.add.f32 [%0], %1;"
                 :: "l"(&g_sumv[(base+tg)*HEADS + h]), "f"(ex) : "memory");
    const float4* vp = (const float4*)(g_v + (size_t)(base+s)*OUTD + h*16);
    float4 v0 = vp[0], v1 = vp[1], v2 = vp[2], v3 = vp[3];
    float* p = g_agg + (size_t)(base+tg)*OUTD + h*16;
    float4 m0; m0.x = ex*v0.x; m0.y = ex*v0.y; m0.z = ex*v0.z; m0.w = ex*v0.w;
    float4 m1; m1.x = ex*v1.x; m1.y = ex*v1.y; m1.z = ex*v1.z; m1.w = ex*v1.w;
    float4 m2; m2.x = ex*v2.x; m2.y = ex*v2.y; m2.z = ex*v2.z; m2.w = ex*v2.w;
    float4 m3; m3.x = ex*v3.x; m3.y = ex*v3.y; m3.z = ex*v3.z; m3.w = ex*v3.w;
    red_add4(p,      m0);
    red_add4(p + 4,  m1);
    red_add4(p + 8,  m2);
    red_add4(p + 12, m3);
}

// ---------------- fused edge pass v2 (gkt): + precomputed g_ae ----------------
__global__ void __launch_bounds__(256) edge_pass_gkt(const int* __restrict__ idx){
    int tid = threadIdx.x;
    int h = tid & 7;
    int e = blockIdx.x*32 + (tid >> 3);
    int base = (e >= NEDGE) ? NNODE : 0;
    int2 st = *(const int2*)(idx + 2*e);
    int s = st.x, tg = st.y;
    float l = g_att1[(base+s)*HEADS + h] + g_att2[(base+tg)*HEADS + h]
              + g_ae[(size_t)e*HEADS + h];
    l = (l > 0.0f) ? l : NEG_SLOPE*l;
    float ex = __expf(l);
    asm volatile("red.global.add.f32 [%0], %1;"
                 :: "l"(&g_sumv[(base+tg)*HEADS + h]), "f"(ex) : "memory");
    const float4* vp = (const float4*)(g_v + (size_t)(base+s)*OUTD + h*16);
    float4 v0 = vp[0], v1 = vp[1], v2 = vp[2], v3 = vp[3];
    float* p = g_agg + (size_t)(base+tg)*OUTD + h*16;
    float4 m0; m0.x = ex*v0.x; m0.y = ex*v0.y; m0.z = ex*v0.z; m0.w = ex*v0.w;
    float4 m1; m1.x = ex*v1.x; m1.y = ex*v1.y; m1.z = ex*v1.z; m1.w = ex*v1.w;
    float4 m2; m2.x = ex*v2.x; m2.y = ex*v2.y; m2.z = ex*v2.z; m2.w = ex*v2.w;
    float4 m3; m3.x = ex*v3.x; m3.y = ex*v3.y; m3.z = ex*v3.z; m3.w = ex*v3.w;
    red_add4(p,      m0);
    red_add4(p + 4,  m1);
    red_add4(p + 8,  m2);
    red_add4(p + 12, m3);
}

// ---------------- finalize: relu(agg/sumv + skip); reset agg/sumv race-free ----------------
__global__ void finalize(float* __restrict__ dstin, int to_hidden2){
    int i = blockIdx.x*blockDim.x + threadIdx.x;
    if (i >= NODES_TOT*OUTD/4) return;
    float* dst = to_hidden2 ? g_hidden2 : dstin;
    int node = i >> 5;
    int head = (i & 31) >> 2;
    float sv = g_sumv[node*HEADS + head];
    __syncwarp();
    if ((i & 3) == 0) g_sumv[node*HEADS + head] = 0.0f;
    float inv = (sv != 0.0f) ? (1.0f / sv) : 0.0f;
    float4 a = ((const float4*)g_agg)[i];
    float4 s = ((const float4*)g_skip)[i];
    float4 o;
    o.x = fmaxf(fmaf(a.x, inv, s.x), 0.0f);
    o.y = fmaxf(fmaf(a.y, inv, s.y), 0.0f);
    o.z = fmaxf(fmaf(a.z, inv, s.z), 0.0f);
    o.w = fmaxf(fmaf(a.w, inv, s.w), 0.0f);
    ((float4*)dst)[i] = o;
    float4 z; z.x = 0.0f; z.y = 0.0f; z.z = 0.0f; z.w = 0.0f;
    ((float4*)g_agg)[i] = z;
}

// ---------------- launch: K-split partials + multi-stream fork/join ----------------
extern "C" void kernel_launch(void* const* d_in, const int* in_sizes, int n_in,
                              void* d_out, int out_size){
    const float* node_fts     = (const float*)d_in[0];
    const float* gkt_edge_fts = (const float*)d_in[1];
    const float* hidden       = (const float*)d_in[2];
    const int*   cfg_idx      = (const int*)d_in[3];
    const int*   gkt_idx      = (const int*)d_in[4];
    const float* Wm    = (const float*)d_in[5];
    const float* bm    = (const float*)d_in[6];
    const float* Wskip = (const float*)d_in[7];
    const float* bskip = (const float*)d_in[8];
    const float* Wa1   = (const float*)d_in[9];
    const float* ba1   = (const float*)d_in[10];
    const float* Wa2   = (const float*)d_in[11];
    const float* ba2   = (const float*)d_in[12];
    const float* Wae   = (const float*)d_in[13];
    const float* bae   = (const float*)d_in[14];
    float* out = (float*)d_out;

    static cudaStream_t s1 = nullptr, s2 = nullptr;
    static cudaEvent_t ev0, evAtt1, evAtt2, evFin1, evAe;
    if (!s1){
        cudaStreamCreateWithFlags(&s1, cudaStreamNonBlocking);
        cudaStreamCreateWithFlags(&s2, cudaStreamNonBlocking);
        cudaEventCreateWithFlags(&ev0,    cudaEventDisableTiming);
        cudaEventCreateWithFlags(&evAtt1, cudaEventDisableTiming);
        cudaEventCreateWithFlags(&evAtt2, cudaEventDisableTiming);
        cudaEventCreateWithFlags(&evFin1, cudaEventDisableTiming);
        cudaEventCreateWithFlags(&evAe,   cudaEventDisableTiming);
        cudaFuncSetAttribute(gemm_node, cudaFuncAttributeMaxDynamicSharedMemorySize, GEMM_SMEM);
    }

    const int TB = 256;
    dim3 gemm_grid(NODES_TOT/128, 2);

    // fork point
    cudaEventRecord(ev0, 0);
    cudaStreamWaitEvent(s1, ev0, 0);
    cudaStreamWaitEvent(s2, ev0, 0);

    build_w<<<(256*256)/TB, TB>>>(Wm, Wskip);                                   // 0 (stream0)
    build_wa<<<(ZDIM*16)/TB, TB, 0, s1>>>(Wa1, Wa2, ba1, ba2);                  // 1 (s1)
    build_wb<<<1, TB>>>(bm, bskip);                                             // 2 (stream0)

    // ---- shared partials (overlapped): pv on 0, attp on s1, ae on s2 ----
    gemm_node<<<gemm_grid, 256, GEMM_SMEM>>>(node_fts, 0);                      // 3 (stream0) <- ncu
    gemm_att<<<NODES_TOT/128, TB, 0, s1>>>(node_fts, 0);                        // 4 (s1)
    ae_gkt<<<EDGES_TOT/(32*AE_TILES_PER_BLK), TB, 0, s2>>>(gkt_edge_fts, Wae, bae); // 5 (s2)
    cudaEventRecord(evAe, s2);

    // ===== stage 1 (cfg): hidden half =====
    gemm_att<<<NODES_TOT/128, TB, 0, s1>>>(hidden, 1);                          // 6 (s1)
    cudaEventRecord(evAtt1, s1);
    gemm_node<<<gemm_grid, 256, GEMM_SMEM>>>(hidden, 1);                        // 7 (stream0)
    cudaStreamWaitEvent(0, evAtt1, 0);
    edge_pass_cfg<<<EDGES_TOT/32, TB>>>(cfg_idx);                               // 8
    finalize<<<(NODES_TOT*OUTD/4)/TB, TB>>>(out, 1);   // -> g_hidden2          // 9
    cudaEventRecord(evFin1, 0);

    // ===== stage 2 (gkt): cfg_hidden half =====
    cudaStreamWaitEvent(s1, evFin1, 0);
    gemm_att<<<NODES_TOT/128, TB, 0, s1>>>(nullptr, 2);                         // 10 (s1)
    cudaEventRecord(evAtt2, s1);
    gemm_node<<<gemm_grid, 256, GEMM_SMEM>>>(nullptr, 2);                       // 11 (stream0)
    cudaStreamWaitEvent(0, evAtt2, 0);
    cudaStreamWaitEvent(0, evAe, 0);
    edge_pass_gkt<<<EDGES_TOT/32, TB>>>(gkt_idx);                               // 12
    finalize<<<(NODES_TOT*OUTD/4)/TB, TB>>>(out, 0);   // -> d_out              // 13
}

// round 17
// speedup vs baseline: 1.0091x; 1.0091x over previous
#include <cuda_runtime.h>
#include <cuda_bf16.h>
#include <math.h>
#include <stdint.h>

#define BATCH   2
#define NNODE   32768
#define DIM     128
#define ZDIM    256
#define OUTD    128
#define HEADS   8
#define NEDGE   262144
#define NODES_TOT (BATCH*NNODE)   /* 65536  */
#define EDGES_TOT (BATCH*NEDGE)   /* 524288 */
#define NEG_SLOPE 0.01f

// ---------------- scratch (static device allocations; no cudaMalloc) ----------------
__device__ float g_att1[NODES_TOT*HEADS];
__device__ float g_att2[NODES_TOT*HEADS];
__device__ float g_v[NODES_TOT*OUTD];
__device__ float g_skip[NODES_TOT*OUTD];
__device__ float g_hidden2[NODES_TOT*OUTD];
__device__ float g_sumv[NODES_TOT*HEADS];   // zero-init; finalize re-zeros (race-free)
__device__ float g_agg[NODES_TOT*OUTD];     // zero-init; finalize re-zeros
__device__ float g_ae[EDGES_TOT*HEADS];     // precomputed ef@Wae + bae
__device__ float g_pv[NODES_TOT*256];       // node_fts @ W[0:128,:]
__device__ float g_attp[NODES_TOT*16];      // node_fts @ Wa[0:128,:]
__device__ float g_bcat[256];
__device__ float g_Wa[ZDIM*16];
__device__ float g_ba[16];
__device__ unsigned short g_Wt_hi[256*256];
__device__ unsigned short g_Wt_lo[256*256];

// ---------------- helpers ----------------
__device__ __forceinline__ uint32_t smem_to_u32(const void* smem_ptr) {
    uint32_t addr;
    asm("{ .reg .u64 tmp; cvta.to.shared.u64 tmp, %1; cvt.u32.u64 %0, tmp; }"
        : "=r"(addr) : "l"(smem_ptr));
    return addr;
}
__device__ __forceinline__ void ldsm4(uint32_t* r, uint32_t addr){
    asm volatile("ldmatrix.sync.aligned.m8n8.x4.shared.b16 {%0,%1,%2,%3}, [%4];"
        : "=r"(r[0]), "=r"(r[1]), "=r"(r[2]), "=r"(r[3]) : "r"(addr));
}
__device__ __forceinline__ void mma_bf16(float* c, const uint32_t* a, uint32_t b0, uint32_t b1){
    asm volatile("mma.sync.aligned.m16n8k16.row.col.f32.bf16.bf16.f32 "
        "{%0,%1,%2,%3}, {%4,%5,%6,%7}, {%8,%9}, {%0,%1,%2,%3};"
        : "+f"(c[0]), "+f"(c[1]), "+f"(c[2]), "+f"(c[3])
        : "r"(a[0]), "r"(a[1]), "r"(a[2]), "r"(a[3]), "r"(b0), "r"(b1));
}
__device__ __forceinline__ void split1(float a, unsigned short& h, unsigned short& l){
    __nv_bfloat16 hb = __float2bfloat16(a);
    __nv_bfloat16 lb = __float2bfloat16(a - __bfloat162float(hb));
    h = __bfloat16_as_ushort(hb); l = __bfloat16_as_ushort(lb);
}
__device__ __forceinline__ uint32_t pack2(unsigned short a, unsigned short b){
    return (uint32_t)a | ((uint32_t)b << 16);
}
__device__ __forceinline__ void cp16(uint32_t dst, const void* src){
    asm volatile("cp.async.ca.shared.global [%0], [%1], 16;" :: "r"(dst), "l"(src));
}
#define CP_COMMIT()  asm volatile("cp.async.commit_group;" ::: "memory")
#define CP_WAIT0()   asm volatile("cp.async.wait_group 0;" ::: "memory")
#define CP_WAIT1()   asm volatile("cp.async.wait_group 1;" ::: "memory")
__device__ __forceinline__ void red_add4(float* p, float4 m){
    asm volatile("red.global.add.v4.f32 [%0], {%1,%2,%3,%4};"
                 :: "l"(p), "f"(m.x), "f"(m.y), "f"(m.z), "f"(m.w) : "memory");
}

// ---------------- weight packing ----------------
__global__ void build_w(const float* __restrict__ Wm, const float* __restrict__ Wskip){
    int i = blockIdx.x*blockDim.x + threadIdx.x;
    if (i < 256*256){
        int n = i >> 8, k = i & 255;
        float w = (n < OUTD) ? Wm[k*OUTD + n] : Wskip[k*OUTD + (n - OUTD)];
        unsigned short h, l;
        split1(w, h, l);
        g_Wt_hi[i] = h; g_Wt_lo[i] = l;
    }
}
__global__ void build_wa(const float* __restrict__ Wa1, const float* __restrict__ Wa2,
                         const float* __restrict__ ba1, const float* __restrict__ ba2){
    int i = blockIdx.x*blockDim.x + threadIdx.x;
    if (i < ZDIM*16){
        int k = i >> 4, j = i & 15;
        g_Wa[i] = (j < HEADS) ? Wa1[k*HEADS + j] : Wa2[k*HEADS + (j-HEADS)];
    }
    if (i < 16) g_ba[i] = (i < HEADS) ? ba1[i] : ba2[i-HEADS];
}
__global__ void build_wb(const float* __restrict__ bm, const float* __restrict__ bskip){
    int i = threadIdx.x;
    if (i < 256) g_bcat[i] = (i < OUTD) ? bm[i] : bskip[i-OUTD];
}

// ---------------- ae precompute: cp.async double-buffered (R13 proven) ----------------
#define AE_TILES_PER_BLK 8
#define AE_BUF_F4 (32*36)
__global__ void __launch_bounds__(256) ae_gkt(const float* __restrict__ ef,
                                              const float* __restrict__ Wae,
                                              const float* __restrict__ bae){
    __shared__ float4 sz[2*AE_BUF_F4];
    const uint32_t sb = smem_to_u32(sz);
    const int tid = threadIdx.x;
    const int lane = tid & 31;
    const int wid = tid >> 5;
    const int q = lane >> 3, h = lane & 7;
    float w[32];
    #pragma unroll
    for (int i = 0; i < 32; i++) w[i] = Wae[(q*32 + i)*HEADS + h];
    const float bb = bae[h];

    const size_t tile0 = (size_t)blockIdx.x * AE_TILES_PER_BLK;

    #pragma unroll
    for (int r = 0; r < 4; r++){
        int f = tid + 256*r;
        int e = f >> 5, j = f & 31;
        uint32_t dst = sb + (uint32_t)(e*36 + (j >> 3)*9 + (j & 7))*16u;
        cp16(dst, ef + (tile0*32 + e)*DIM + j*4);
    }
    CP_COMMIT();

    #pragma unroll 1
    for (int t = 0; t < AE_TILES_PER_BLK; t++){
        if (t + 1 < AE_TILES_PER_BLK){
            uint32_t bufo = ((t+1) & 1) ? (uint32_t)AE_BUF_F4*16u : 0u;
            #pragma unroll
            for (int r = 0; r < 4; r++){
                int f = tid + 256*r;
                int e = f >> 5, j = f & 31;
                uint32_t dst = sb + bufo + (uint32_t)(e*36 + (j >> 3)*9 + (j & 7))*16u;
                cp16(dst, ef + ((tile0 + t + 1)*32 + e)*DIM + j*4);
            }
            CP_COMMIT();
            CP_WAIT1();
        } else {
            CP_WAIT0();
        }
        __syncthreads();

        const float4* buf = sz + ((t & 1) ? AE_BUF_F4 : 0);
        #pragma unroll
        for (int eo = 0; eo < 4; eo++){
            int el = wid*4 + eo;
            float acc = 0.0f;
            #pragma unroll
            for (int i = 0; i < 8; i++){
                float4 v = buf[el*36 + q*9 + i];
                acc += v.x*w[4*i] + v.y*w[4*i+1] + v.z*w[4*i+2] + v.w*w[4*i+3];
            }
            acc += __shfl_xor_sync(0xffffffffu, acc, 8);
            acc += __shfl_xor_sync(0xffffffffu, acc, 16);
            if (lane < 8) g_ae[((tile0 + t)*32 + el)*HEADS + h] = acc + bb;
        }
        __syncthreads();
    }
}

// ================= node GEMM (K=128 half): mma.sync bf16 3-term ==================
// A double-buffered in smem; fp32->bf16 convert of chunk kc+1 runs in the compute
// shadow of chunk kc (FMA pipe overlaps tensor pipe). B cp.async double-buffered.
// mode 0: f=node_fts, W k-range [0,128), raw -> g_pv
// mode 1: f=hidden,   [128,256), out = acc + g_pv + bias -> v|skip
// mode 2: f=g_hidden2, same as mode 1
#define A_BUF_SZ   20480      /* hi 10240 + lo 10240 */
#define SM_B0      40960
#define B_BUF_SZ   20480      /* hi 10240 + lo 10240 */
#define GEMM_SMEM  81920

__global__ void __launch_bounds__(256, 2) gemm_node(const float* __restrict__ fin, int mode){
    const float* f = (mode == 2) ? g_hidden2 : fin;
    const int koffB = (mode == 0) ? 0 : 128;
    extern __shared__ char sm[];
    const uint32_t sb = smem_to_u32(sm);
    const int tid  = threadIdx.x;
    const int lane = tid & 31;
    const int wid  = tid >> 5;
    const int wm   = (wid >> 1) * 32;
    const int wn   = (wid & 1) * 64;
    const int row0g = blockIdx.x * 128;
    const int n0g   = blockIdx.y * 128;

    float acc[2][8][4];
    #pragma unroll
    for (int a = 0; a < 2; a++)
        #pragma unroll
        for (int b = 0; b < 8; b++)
            #pragma unroll
            for (int c = 0; c < 4; c++) acc[a][b][c] = 0.0f;

    const int arow = tid >> 1, ah16 = (tid & 1) * 16;
    const int bn = tid >> 1,  hb = tid & 1;
    const int grp = lane >> 3, wi = lane & 7;

    // ---- prologue: cp B0; LDG+convert A0 -> Abuf0 ----
    {
        uint32_t bdst = sb + SM_B0 + bn*80 + hb*32;
        const unsigned short* src_h = g_Wt_hi + (size_t)(n0g + bn)*256 + koffB + hb*16;
        const unsigned short* src_l = g_Wt_lo + (size_t)(n0g + bn)*256 + koffB + hb*16;
        cp16(bdst,              src_h);
        cp16(bdst + 16,         src_h + 8);
        cp16(bdst + 10240,      src_l);
        cp16(bdst + 10240 + 16, src_l + 8);
        CP_COMMIT();
    }
    float4 ap0, ap1, ap2, ap3;
    {
        const float* ap = f + (size_t)(row0g + arow)*DIM + ah16;
        ap0 = *(const float4*)ap;       ap1 = *(const float4*)(ap + 4);
        ap2 = *(const float4*)(ap + 8); ap3 = *(const float4*)(ap + 12);
    }
    {   // convert A0 into Abuf0
        unsigned short h[16], l[16];
        split1(ap0.x, h[0], l[0]);  split1(ap0.y, h[1], l[1]);
        split1(ap0.z, h[2], l[2]);  split1(ap0.w, h[3], l[3]);
        split1(ap1.x, h[4], l[4]);  split1(ap1.y, h[5], l[5]);
        split1(ap1.z, h[6], l[6]);  split1(ap1.w, h[7], l[7]);
        split1(ap2.x, h[8], l[8]);  split1(ap2.y, h[9], l[9]);
        split1(ap2.z, h[10],l[10]); split1(ap2.w, h[11],l[11]);
        split1(ap3.x, h[12],l[12]); split1(ap3.y, h[13],l[13]);
        split1(ap3.z, h[14],l[14]); split1(ap3.w, h[15],l[15]);
        uint4 hh0, hh1, ll0, ll1;
        hh0.x = pack2(h[0],h[1]);   hh0.y = pack2(h[2],h[3]);
        hh0.z = pack2(h[4],h[5]);   hh0.w = pack2(h[6],h[7]);
        hh1.x = pack2(h[8],h[9]);   hh1.y = pack2(h[10],h[11]);
        hh1.z = pack2(h[12],h[13]); hh1.w = pack2(h[14],h[15]);
        ll0.x = pack2(l[0],l[1]);   ll0.y = pack2(l[2],l[3]);
        ll0.z = pack2(l[4],l[5]);   ll0.w = pack2(l[6],l[7]);
        ll1.x = pack2(l[8],l[9]);   ll1.y = pack2(l[10],l[11]);
        ll1.z = pack2(l[12],l[13]); ll1.w = pack2(l[14],l[15]);
        *(uint4*)(sm + arow*80 + ah16*2)          = hh0;
        *(uint4*)(sm + arow*80 + ah16*2 + 16)     = hh1;
        *(uint4*)(sm + 10240 + arow*80 + ah16*2)      = ll0;
        *(uint4*)(sm + 10240 + arow*80 + ah16*2 + 16) = ll1;
    }

    for (int kc = 0; kc < 4; kc++){
        const uint32_t abase = (uint32_t)((kc & 1)*A_BUF_SZ);
        const uint32_t bbase = sb + SM_B0 + (kc & 1)*B_BUF_SZ;

        CP_WAIT0();            // B[kc] resident
        __syncthreads();       // Abuf[kc]/B[kc] visible; prev compute done -> other bufs reusable

        if (kc < 3){
            // prefetch B[kc+1] into the other B buffer
            uint32_t bdst = sb + SM_B0 + ((kc+1) & 1)*B_BUF_SZ + bn*80 + hb*32;
            const unsigned short* src_h = g_Wt_hi + (size_t)(n0g + bn)*256 + koffB + (kc+1)*32 + hb*16;
            const unsigned short* src_l = g_Wt_lo + (size_t)(n0g + bn)*256 + koffB + (kc+1)*32 + hb*16;
            cp16(bdst,              src_h);
            cp16(bdst + 16,         src_h + 8);
            cp16(bdst + 10240,      src_l);
            cp16(bdst + 10240 + 16, src_l + 8);
            CP_COMMIT();
            // prefetch A[kc+1] into regs (LDG latency hidden by compute below)
            const float* ap = f + (size_t)(row0g + arow)*DIM + (kc+1)*32 + ah16;
            ap0 = *(const float4*)ap;       ap1 = *(const float4*)(ap + 4);
            ap2 = *(const float4*)(ap + 8); ap3 = *(const float4*)(ap + 12);
        }

        // ---- compute chunk kc (tensor pipe) ----
        #pragma unroll
        for (int ks = 0; ks < 2; ks++){
            const int kb = ks*16;
            uint32_t ahr[2][4], alr[2][4];
            #pragma unroll
            for (int mt = 0; mt < 2; mt++){
                int r = wm + mt*16 + wi + (grp & 1)*8;
                int c = kb + (grp >> 1)*8;
                uint32_t adr = sb + abase + r*80 + c*2;
                ldsm4(ahr[mt], adr);
                ldsm4(alr[mt], adr + 10240);
            }
            #pragma unroll
            for (int np = 0; np < 4; np++){
                int rb = wn + np*16 + wi + (grp >> 1)*8;
                int cb = kb + (grp & 1)*8;
                uint32_t badr = bbase + rb*80 + cb*2;
                uint32_t bh[4], bl[4];
                ldsm4(bh, badr);
                ldsm4(bl, badr + 10240);
                #pragma unroll
                for (int mt = 0; mt < 2; mt++){
                    #pragma unroll
                    for (int nt = 0; nt < 2; nt++){
                        float* C = acc[mt][np*2 + nt];
                        mma_bf16(C, ahr[mt], bh[nt*2], bh[nt*2+1]);
                        mma_bf16(C, alr[mt], bh[nt*2], bh[nt*2+1]);
                        mma_bf16(C, ahr[mt], bl[nt*2], bl[nt*2+1]);
                    }
                }
            }
        }

        // ---- convert A[kc+1] in the compute shadow (FMA pipe; no sync needed here) ----
        if (kc < 3){
            const uint32_t anext = (uint32_t)(((kc+1) & 1)*A_BUF_SZ);
            unsigned short h[16], l[16];
            split1(ap0.x, h[0], l[0]);  split1(ap0.y, h[1], l[1]);
            split1(ap0.z, h[2], l[2]);  split1(ap0.w, h[3], l[3]);
            split1(ap1.x, h[4], l[4]);  split1(ap1.y, h[5], l[5]);
            split1(ap1.z, h[6], l[6]);  split1(ap1.w, h[7], l[7]);
            split1(ap2.x, h[8], l[8]);  split1(ap2.y, h[9], l[9]);
            split1(ap2.z, h[10],l[10]); split1(ap2.w, h[11],l[11]);
            split1(ap3.x, h[12],l[12]); split1(ap3.y, h[13],l[13]);
            split1(ap3.z, h[14],l[14]); split1(ap3.w, h[15],l[15]);
            uint4 hh0, hh1, ll0, ll1;
            hh0.x = pack2(h[0],h[1]);   hh0.y = pack2(h[2],h[3]);
            hh0.z = pack2(h[4],h[5]);   hh0.w = pack2(h[6],h[7]);
            hh1.x = pack2(h[8],h[9]);   hh1.y = pack2(h[10],h[11]);
            hh1.z = pack2(h[12],h[13]); hh1.w = pack2(h[14],h[15]);
            ll0.x = pack2(l[0],l[1]);   ll0.y = pack2(l[2],l[3]);
            ll0.z = pack2(l[4],l[5]);   ll0.w = pack2(l[6],l[7]);
            ll1.x = pack2(l[8],l[9]);   ll1.y = pack2(l[10],l[11]);
            ll1.z = pack2(l[12],l[13]); ll1.w = pack2(l[14],l[15]);
            *(uint4*)(sm + anext + arow*80 + ah16*2)          = hh0;
            *(uint4*)(sm + anext + arow*80 + ah16*2 + 16)     = hh1;
            *(uint4*)(sm + anext + 10240 + arow*80 + ah16*2)      = ll0;
            *(uint4*)(sm + anext + 10240 + arow*80 + ah16*2 + 16) = ll1;
        }
    }

    // ---- epilogue ----
    const int gid = lane >> 2, tc = lane & 3;
    if (mode == 0){
        #pragma unroll
        for (int mt = 0; mt < 2; mt++){
            int r0 = row0g + wm + mt*16 + gid;
            #pragma unroll
            for (int np = 0; np < 4; np++){
                #pragma unroll
                for (int nt = 0; nt < 2; nt++){
                    int col = n0g + wn + np*16 + nt*8 + tc*2;
                    float* C = acc[mt][np*2 + nt];
                    float2 o0; o0.x = C[0]; o0.y = C[1];
                    float2 o1; o1.x = C[2]; o1.y = C[3];
                    *(float2*)(g_pv + (size_t)r0*256 + col)     = o0;
                    *(float2*)(g_pv + (size_t)(r0+8)*256 + col) = o1;
                }
            }
        }
    } else {
        #pragma unroll
        for (int mt = 0; mt < 2; mt++){
            int r0 = row0g + wm + mt*16 + gid;
            #pragma unroll
            for (int np = 0; np < 4; np++){
                #pragma unroll
                for (int nt = 0; nt < 2; nt++){
                    int col = n0g + wn + np*16 + nt*8 + tc*2;
                    float* dst = (col < 128) ? g_v : g_skip;
                    int cl = col & 127;
                    float b0 = g_bcat[col], b1 = g_bcat[col + 1];
                    float2 p0 = *(const float2*)(g_pv + (size_t)r0*256 + col);
                    float2 p1 = *(const float2*)(g_pv + (size_t)(r0+8)*256 + col);
                    float* C = acc[mt][np*2 + nt];
                    float2 o0; o0.x = C[0] + p0.x + b0; o0.y = C[1] + p0.y + b1;
                    float2 o1; o1.x = C[2] + p1.x + b0; o1.y = C[3] + p1.y + b1;
                    *(float2*)(dst + (size_t)r0*OUTD + cl)     = o0;
                    *(float2*)(dst + (size_t)(r0+8)*OUTD + cl) = o1;
                }
            }
        }
    }
}

// ---------------- attention-vector GEMM (K=128 half) ----------------
__global__ void __launch_bounds__(256) gemm_att(const float* __restrict__ fin, int mode){
    const float* base = (mode == 2) ? g_hidden2 : fin;
    const int koff = (mode == 0) ? 0 : 128;
    __shared__ float As2[128][36];
    __shared__ float Bs[32][16];
    const int t = threadIdx.x;
    const int row0 = blockIdx.x * 128;
    const int my = t >> 1, tx = t & 1;
    float acc[8] = {0,0,0,0,0,0,0,0};

    for (int kc = 0; kc < DIM; kc += 32){
        #pragma unroll
        for (int i = 0; i < 4; i++){
            int id = t + 256*i;
            int r = id >> 3, q = id & 7;
            float4 g = *(const float4*)(base + (size_t)(row0 + r)*DIM + kc + q*4);
            *(float4*)(&As2[r][q*4]) = g;
        }
        if (t < 128){
            int kk = t >> 2, j4 = (t & 3)*4;
            *(float4*)(&Bs[kk][j4]) = *(const float4*)(g_Wa + (koff + kc + kk)*16 + j4);
        }
        __syncthreads();
        #pragma unroll
        for (int kk = 0; kk < 32; kk++){
            float a = As2[my][kk];
            float4 b0 = *(float4*)(&Bs[kk][tx*8]);
            float4 b1 = *(float4*)(&Bs[kk][tx*8 + 4]);
            acc[0] = fmaf(a, b0.x, acc[0]); acc[1] = fmaf(a, b0.y, acc[1]);
            acc[2] = fmaf(a, b0.z, acc[2]); acc[3] = fmaf(a, b0.w, acc[3]);
            acc[4] = fmaf(a, b1.x, acc[4]); acc[5] = fmaf(a, b1.y, acc[5]);
            acc[6] = fmaf(a, b1.z, acc[6]); acc[7] = fmaf(a, b1.w, acc[7]);
        }
        __syncthreads();
    }

    int row = row0 + my;
    if (mode == 0){
        #pragma unroll
        for (int jj = 0; jj < 8; jj++)
            g_attp[row*16 + tx*8 + jj] = acc[jj];
    } else {
        #pragma unroll
        for (int jj = 0; jj < 8; jj++){
            int j = tx*8 + jj;
            float v = acc[jj] + g_attp[row*16 + j] + g_ba[j];
            if (j < HEADS) g_att1[row*HEADS + j] = v;
            else           g_att2[row*HEADS + (j-HEADS)] = v;
        }
    }
}

// ---------------- fused edge pass v2 (cfg): 8 threads/edge ----------------
__global__ void __launch_bounds__(256) edge_pass_cfg(const int* __restrict__ idx){
    int tid = threadIdx.x;
    int h = tid & 7;
    int e = blockIdx.x*32 + (tid >> 3);
    int base = (e >= NEDGE) ? NNODE : 0;
    int2 st = *(const int2*)(idx + 2*e);
    int s = st.x, tg = st.y;
    float l = g_att1[(base+s)*HEADS + h] + g_att2[(base+tg)*HEADS + h];
    l = (l > 0.0f) ? l : NEG_SLOPE*l;
    float ex = __expf(l);
    asm volatile("red.global.add.f32 [%0], %1;"
                 :: "l"(&g_sumv[(base+tg)*HEADS + h]), "f"(ex) : "memory");
    const float4* vp = (const float4*)(g_v + (size_t)(base+s)*OUTD + h*16);
    float4 v0 = vp[0], v1 = vp[1], v2 = vp[2], v3 = vp[3];
    float* p = g_agg + (size_t)(base+tg)*OUTD + h*16;
    float4 m0; m0.x = ex*v0.x; m0.y = ex*v0.y; m0.z = ex*v0.z; m0.w = ex*v0.w;
    float4 m1; m1.x = ex*v1.x; m1.y = ex*v1.y; m1.z = ex*v1.z; m1.w = ex*v1.w;
    float4 m2; m2.x = ex*v2.x; m2.y = ex*v2.y; m2.z = ex*v2.z; m2.w = ex*v2.w;
    float4 m3; m3.x = ex*v3.x; m3.y = ex*v3.y; m3.z = ex*v3.z; m3.w = ex*v3.w;
    red_add4(p,      m0);
    red_add4(p + 4,  m1);
    red_add4(p + 8,  m2);
    red_add4(p + 12, m3);
}

// ---------------- fused edge pass v2 (gkt): + precomputed g_ae ----------------
__global__ void __launch_bounds__(256) edge_pass_gkt(const int* __restrict__ idx){
    int tid = threadIdx.x;
    int h = tid & 7;
    int e = blockIdx.x*32 + (tid >> 3);
    int base = (e >= NEDGE) ? NNODE : 0;
    int2 st = *(const int2*)(idx + 2*e);
    int s = st.x, tg = st.y;
    float l = g_att1[(base+s)*HEADS + h] + g_att2[(base+tg)*HEADS + h]
              + g_ae[(size_t)e*HEADS + h];
    l = (l > 0.0f) ? l : NEG_SLOPE*l;
    float ex = __expf(l);
    asm volatile("red.global.add.f32 [%0], %1;"
                 :: "l"(&g_sumv[(base+tg)*HEADS + h]), "f"(ex) : "memory");
    const float4* vp = (const float4*)(g_v + (size_t)(base+s)*OUTD + h*16);
    float4 v0 = vp[0], v1 = vp[1], v2 = vp[2], v3 = vp[3];
    float* p = g_agg + (size_t)(base+tg)*OUTD + h*16;
    float4 m0; m0.x = ex*v0.x; m0.y = ex*v0.y; m0.z = ex*v0.z; m0.w = ex*v0.w;
    float4 m1; m1.x = ex*v1.x; m1.y = ex*v1.y; m1.z = ex*v1.z; m1.w = ex*v1.w;
    float4 m2; m2.x = ex*v2.x; m2.y = ex*v2.y; m2.z = ex*v2.z; m2.w = ex*v2.w;
    float4 m3; m3.x = ex*v3.x; m3.y = ex*v3.y; m3.z = ex*v3.z; m3.w = ex*v3.w;
    red_add4(p,      m0);
    red_add4(p + 4,  m1);
    red_add4(p + 8,  m2);
    red_add4(p + 12, m3);
}

// ---------------- finalize: relu(agg/sumv + skip); reset agg/sumv race-free ----------------
__global__ void finalize(float* __restrict__ dstin, int to_hidden2){
    int i = blockIdx.x*blockDim.x + threadIdx.x;
    if (i >= NODES_TOT*OUTD/4) return;
    float* dst = to_hidden2 ? g_hidden2 : dstin;
    int node = i >> 5;
    int head = (i & 31) >> 2;
    float sv = g_sumv[node*HEADS + head];
    __syncwarp();
    if ((i & 3) == 0) g_sumv[node*HEADS + head] = 0.0f;
    float inv = (sv != 0.0f) ? (1.0f / sv) : 0.0f;
    float4 a = ((const float4*)g_agg)[i];
    float4 s = ((const float4*)g_skip)[i];
    float4 o;
    o.x = fmaxf(fmaf(a.x, inv, s.x), 0.0f);
    o.y = fmaxf(fmaf(a.y, inv, s.y), 0.0f);
    o.z = fmaxf(fmaf(a.z, inv, s.z), 0.0f);
    o.w = fmaxf(fmaf(a.w, inv, s.w), 0.0f);
    ((float4*)dst)[i] = o;
    float4 z; z.x = 0.0f; z.y = 0.0f; z.z = 0.0f; z.w = 0.0f;
    ((float4*)g_agg)[i] = z;
}

// ---------------- launch: K-split partials + multi-stream fork/join ----------------
extern "C" void kernel_launch(void* const* d_in, const int* in_sizes, int n_in,
                              void* d_out, int out_size){
    const float* node_fts     = (const float*)d_in[0];
    const float* gkt_edge_fts = (const float*)d_in[1];
    const float* hidden       = (const float*)d_in[2];
    const int*   cfg_idx      = (const int*)d_in[3];
    const int*   gkt_idx      = (const int*)d_in[4];
    const float* Wm    = (const float*)d_in[5];
    const float* bm    = (const float*)d_in[6];
    const float* Wskip = (const float*)d_in[7];
    const float* bskip = (const float*)d_in[8];
    const float* Wa1   = (const float*)d_in[9];
    const float* ba1   = (const float*)d_in[10];
    const float* Wa2   = (const float*)d_in[11];
    const float* ba2   = (const float*)d_in[12];
    const float* Wae   = (const float*)d_in[13];
    const float* bae   = (const float*)d_in[14];
    float* out = (float*)d_out;

    static cudaStream_t s1 = nullptr, s2 = nullptr;
    static cudaEvent_t ev0, evAtt1, evAtt2, evFin1, evAe;
    if (!s1){
        cudaStreamCreateWithFlags(&s1, cudaStreamNonBlocking);
        cudaStreamCreateWithFlags(&s2, cudaStreamNonBlocking);
        cudaEventCreateWithFlags(&ev0,    cudaEventDisableTiming);
        cudaEventCreateWithFlags(&evAtt1, cudaEventDisableTiming);
        cudaEventCreateWithFlags(&evAtt2, cudaEventDisableTiming);
        cudaEventCreateWithFlags(&evFin1, cudaEventDisableTiming);
        cudaEventCreateWithFlags(&evAe,   cudaEventDisableTiming);
        cudaFuncSetAttribute(gemm_node, cudaFuncAttributeMaxDynamicSharedMemorySize, GEMM_SMEM);
    }

    const int TB = 256;
    dim3 gemm_grid(NODES_TOT/128, 2);

    // fork point
    cudaEventRecord(ev0, 0);
    cudaStreamWaitEvent(s1, ev0, 0);
    cudaStreamWaitEvent(s2, ev0, 0);

    build_w<<<(256*256)/TB, TB>>>(Wm, Wskip);                                   // 0 (stream0)
    build_wa<<<(ZDIM*16)/TB, TB, 0, s1>>>(Wa1, Wa2, ba1, ba2);                  // 1 (s1)
    build_wb<<<1, TB>>>(bm, bskip);                                             // 2 (stream0)

    // ---- shared partials (overlapped): pv on 0, attp on s1, ae on s2 ----
    gemm_node<<<gemm_grid, 256, GEMM_SMEM>>>(node_fts, 0);                      // 3 (stream0) <- ncu
    gemm_att<<<NODES_TOT/128, TB, 0, s1>>>(node_fts, 0);                        // 4 (s1)
    ae_gkt<<<EDGES_TOT/(32*AE_TILES_PER_BLK), TB, 0, s2>>>(gkt_edge_fts, Wae, bae); // 5 (s2)
    cudaEventRecord(evAe, s2);

    // ===== stage 1 (cfg): hidden half =====
    gemm_att<<<NODES_TOT/128, TB, 0, s1>>>(hidden, 1);                          // 6 (s1)
    cudaEventRecord(evAtt1, s1);
    gemm_node<<<gemm_grid, 256, GEMM_SMEM>>>(hidden, 1);                        // 7 (stream0)
    cudaStreamWaitEvent(0, evAtt1, 0);
    edge_pass_cfg<<<EDGES_TOT/32, TB>>>(cfg_idx);                               // 8
    finalize<<<(NODES_TOT*OUTD/4)/TB, TB>>>(out, 1);   // -> g_hidden2          // 9
    cudaEventRecord(evFin1, 0);

    // ===== stage 2 (gkt): cfg_hidden half =====
    cudaStreamWaitEvent(s1, evFin1, 0);
    gemm_att<<<NODES_TOT/128, TB, 0, s1>>>(nullptr, 2);                         // 10 (s1)
    cudaEventRecord(evAtt2, s1);
    gemm_node<<<gemm_grid, 256, GEMM_SMEM>>>(nullptr, 2);                       // 11 (stream0)
    cudaStreamWaitEvent(0, evAtt2, 0);
    cudaStreamWaitEvent(0, evAe, 0);
    edge_pass_gkt<<<EDGES_TOT/32, TB>>>(gkt_idx);                               // 12
    finalize<<<(NODES_TOT*OUTD/4)/TB, TB>>>(out, 0);   // -> d_out              // 13
}